// round 14
// baseline (speedup 1.0000x reference)
#include <cuda_runtime.h>
#include <cuda_bf16.h>
#include <cuda_fp16.h>
#include <cstdint>

#define NMAX 100000
#define EMAX 1600000

// ---------------- scratch ----------------
__device__ __nv_bfloat162 g_pb[NMAX * 64];   // p compressed to bf16 (gather operand)
__device__ __half2 g_hh[NMAX * 64];          // h compressed to fp16 (gather operand)
__device__ float g_s [NMAX * 128];
__device__ float g_q [NMAX * 128];
__device__ float g_zp[NMAX * 128];           // fsrc@wz + bz
__device__ float g_cp[NMAX * 128];           // fsrc@w  + b
__device__ int   g_cnt[NMAX];
__device__ int   g_off[NMAX + 1];
__device__ int   g_cur[NMAX];
__device__ int   g_perm[EMAX];
__device__ int   g_bsum[128];
__device__ int   g_bpre[128];
__device__ uint4 g_wimg[6 * 4096];   // 6 weight images, 64KB each, B-fragment order

__device__ __forceinline__ float sigmoidf(float x) { return 1.0f / (1.0f + __expf(-x)); }
__device__ __forceinline__ float tanh_fast(float x) {
    return __fdividef(2.0f, 1.0f + __expf(-2.0f * x)) - 1.0f;
}
__device__ __forceinline__ uint32_t totf32(float f) {
    uint32_t r; asm("cvt.rna.tf32.f32 %0,%1;" : "=r"(r) : "f"(f)); return r;
}

// ---------------- mma.sync m16n8k8 tf32 ----------------
__device__ __forceinline__ void mma8(float* d, const uint32_t* a, uint32_t b0, uint32_t b1) {
    asm("mma.sync.aligned.m16n8k8.row.col.f32.tf32.tf32.f32 "
        "{%0,%1,%2,%3},{%4,%5,%6,%7},{%8,%9},{%0,%1,%2,%3};"
        : "+f"(d[0]), "+f"(d[1]), "+f"(d[2]), "+f"(d[3])
        : "r"(a[0]), "r"(a[1]), "r"(a[2]), "r"(a[3]), "r"(b0), "r"(b1));
}

// ---------------- fused: h -> fp16 compression + counter zero ----------------
__global__ void k_hzero(const float* __restrict__ h, int n) {
    int i = blockIdx.x * blockDim.x + threadIdx.x;
    if (i < n * 32) {
        float4 v = ((const float4*)h)[i];
        g_hh[i * 2 + 0] = __floats2half2_rn(v.x, v.y);
        g_hh[i * 2 + 1] = __floats2half2_rn(v.z, v.w);
    }
    if (i < n) g_cnt[i] = 0;
}

// ---------------- CSR build ----------------
__global__ void k_hist(const int* __restrict__ dst, int e) {
    int i = blockIdx.x * blockDim.x + threadIdx.x;
    if (i < e) atomicAdd(&g_cnt[dst[i]], 1);
}

__global__ void k_part(int n) {
    __shared__ int sm[1024];
    int b = blockIdx.x, t = threadIdx.x;
    int idx = b * 1024 + t;
    int v = (idx < n) ? g_cnt[idx] : 0;
    sm[t] = v;
    __syncthreads();
    #pragma unroll
    for (int off = 1; off < 1024; off <<= 1) {
        int x = (t >= off) ? sm[t - off] : 0;
        __syncthreads();
        sm[t] += x;
        __syncthreads();
    }
    if (idx < n) g_off[idx] = sm[t] - v;
    if (t == 1023) g_bsum[b] = sm[t];
}

__global__ void k_scanb(int nb) {
    __shared__ int sm[128];
    int t = threadIdx.x;
    int v = (t < nb) ? g_bsum[t] : 0;
    sm[t] = v;
    __syncthreads();
    #pragma unroll
    for (int off = 1; off < 128; off <<= 1) {
        int x = (t >= off) ? sm[t - off] : 0;
        __syncthreads();
        sm[t] += x;
        __syncthreads();
    }
    if (t < nb) g_bpre[t] = sm[t] - v;
}

__global__ void k_add(int n, int e) {
    int idx = blockIdx.x * blockDim.x + threadIdx.x;
    if (idx < n) {
        int o = g_off[idx] + g_bpre[idx >> 10];
        g_off[idx] = o;
        g_cur[idx] = o;
    }
    if (idx == 0) g_off[n] = e;
}

__global__ void k_scatter(const int* __restrict__ src, const int* __restrict__ dst, int e) {
    int i = blockIdx.x * blockDim.x + threadIdx.x;
    if (i < e) {
        int d = dst[i];
        int pos = atomicAdd(&g_cur[d], 1);
        g_perm[pos] = src[i];
    }
}

// ---------------- segment reduce, split, 8-deep gather pipeline ----------------
__global__ void k_reduceS(int n) {
    int gw = (blockIdx.x * blockDim.x + threadIdx.x) >> 5;
    int lane = threadIdx.x & 31;
    if (gw >= n) return;
    int i0 = g_off[gw], i1 = g_off[gw + 1];
    const uint2* hh = (const uint2*)g_hh;
    float4 sa = make_float4(0.f, 0.f, 0.f, 0.f);
    int i = i0;
    for (; i + 7 < i1; i += 8) {
        uint2 b[8];
        #pragma unroll
        for (int k = 0; k < 8; k++) b[k] = hh[g_perm[i + k] * 32 + lane];
        #pragma unroll
        for (int k = 0; k < 8; k++) {
            float2 f = __half22float2(*(__half2*)&b[k].x);
            float2 g = __half22float2(*(__half2*)&b[k].y);
            sa.x += f.x; sa.y += f.y; sa.z += g.x; sa.w += g.y;
        }
    }
    for (; i + 3 < i1; i += 4) {
        uint2 b[4];
        #pragma unroll
        for (int k = 0; k < 4; k++) b[k] = hh[g_perm[i + k] * 32 + lane];
        #pragma unroll
        for (int k = 0; k < 4; k++) {
            float2 f = __half22float2(*(__half2*)&b[k].x);
            float2 g = __half22float2(*(__half2*)&b[k].y);
            sa.x += f.x; sa.y += f.y; sa.z += g.x; sa.w += g.y;
        }
    }
    for (; i < i1; i++) {
        uint2 b0 = hh[g_perm[i] * 32 + lane];
        float2 f = __half22float2(*(__half2*)&b0.x);
        float2 g = __half22float2(*(__half2*)&b0.y);
        sa.x += f.x; sa.y += f.y; sa.z += g.x; sa.w += g.y;
    }
    ((float4*)g_s)[gw * 32 + lane] = sa;
}

__global__ void k_reduceQ(int n) {
    int gw = (blockIdx.x * blockDim.x + threadIdx.x) >> 5;
    int lane = threadIdx.x & 31;
    if (gw >= n) return;
    int i0 = g_off[gw], i1 = g_off[gw + 1];
    const uint2* pb = (const uint2*)g_pb;
    float4 qa = make_float4(0.f, 0.f, 0.f, 0.f);
    int i = i0;
    for (; i + 7 < i1; i += 8) {
        uint2 b[8];
        #pragma unroll
        for (int k = 0; k < 8; k++) b[k] = pb[g_perm[i + k] * 32 + lane];
        #pragma unroll
        for (int k = 0; k < 8; k++) {
            float2 f = __bfloat1622float2(*(__nv_bfloat162*)&b[k].x);
            float2 g = __bfloat1622float2(*(__nv_bfloat162*)&b[k].y);
            qa.x += f.x; qa.y += f.y; qa.z += g.x; qa.w += g.y;
        }
    }
    for (; i + 3 < i1; i += 4) {
        uint2 b[4];
        #pragma unroll
        for (int k = 0; k < 4; k++) b[k] = pb[g_perm[i + k] * 32 + lane];
        #pragma unroll
        for (int k = 0; k < 4; k++) {
            float2 f = __bfloat1622float2(*(__nv_bfloat162*)&b[k].x);
            float2 g = __bfloat1622float2(*(__nv_bfloat162*)&b[k].y);
            qa.x += f.x; qa.y += f.y; qa.z += g.x; qa.w += g.y;
        }
    }
    for (; i < i1; i++) {
        uint2 b0 = pb[g_perm[i] * 32 + lane];
        float2 f = __bfloat1622float2(*(__nv_bfloat162*)&b0.x);
        float2 g = __bfloat1622float2(*(__nv_bfloat162*)&b0.y);
        qa.x += f.x; qa.y += f.y; qa.z += g.x; qa.w += g.y;
    }
    ((float4*)g_q)[gw * 32 + lane] = qa;
}

// ---------------- weight fragment image prep ----------------
__global__ void k_prep(const float* w0, const float* w1, const float* w2,
                       const float* w3, const float* w4, const float* w5) {
    int mat = blockIdx.y;
    int t = blockIdx.x * 256 + threadIdx.x;
    if (t >= 4096) return;
    const float* srcs[6] = {w0, w1, w2, w3, w4, w5};
    const float* W = srcs[mat];
    int nt = t >> 8, kp = (t >> 5) & 7, lane = t & 31;
    int n = nt * 8 + (lane >> 2);
    int kb = kp * 16 + (lane & 3);
    uint4 v;
    v.x = totf32(W[(kb + 0)  * 128 + n]);
    v.y = totf32(W[(kb + 4)  * 128 + n]);
    v.z = totf32(W[(kb + 8)  * 128 + n]);
    v.w = totf32(W[(kb + 12) * 128 + n]);
    g_wimg[mat * 4096 + t] = v;
}

// ---------------- GEMM layouts ----------------
#define XP    132
#define SM_B  (128 * XP * 4)        // 67584 (gemmB/gemmA, fits 2 blocks/SM for 256thr)
#define SM_C  (2 * 128 * XP * 4)    // 135168 (gemmC, 512 thr, 1 block/SM)

template<int NT>
__device__ __forceinline__ void load_xT(float* sX, const float* __restrict__ x,
                                        int rowBase, int n, int tid) {
    const float4* s4 = (const float4*)x;
    #pragma unroll 4
    for (int i = tid; i < 4096; i += NT) {
        int m = i >> 5, c4 = i & 31;
        float4 v = (rowBase + m < n) ? s4[(size_t)(rowBase + m) * 32 + c4]
                                     : make_float4(0.f, 0.f, 0.f, 0.f);
        uint4 o;
        o.x = totf32(v.x); o.y = totf32(v.y); o.z = totf32(v.z); o.w = totf32(v.w);
        *(uint4*)(&sX[m * XP + c4 * 4]) = o;
    }
}

// ---- 256-thread (8 warp, 2(wn) x 4(wm)) product: 64-col slab, d[2][8][4] ----
__device__ __forceinline__ void product8(const float* sX, const uint4* __restrict__ gW,
                                         float d[2][8][4], int wm, int wn, int lane) {
    int r0a = (wm * 2 + 0) * 16 + (lane >> 2);
    int r0b = (wm * 2 + 1) * 16 + (lane >> 2);
    int kl = lane & 3;
    for (int kp = 0; kp < 8; kp++) {
        uint32_t a[2][2][4];
        #pragma unroll
        for (int s = 0; s < 2; s++) {
            int k0 = (kp * 2 + s) * 8 + kl;
            a[0][s][0] = __float_as_uint(sX[r0a * XP + k0]);
            a[0][s][1] = __float_as_uint(sX[(r0a + 8) * XP + k0]);
            a[0][s][2] = __float_as_uint(sX[r0a * XP + k0 + 4]);
            a[0][s][3] = __float_as_uint(sX[(r0a + 8) * XP + k0 + 4]);
            a[1][s][0] = __float_as_uint(sX[r0b * XP + k0]);
            a[1][s][1] = __float_as_uint(sX[(r0b + 8) * XP + k0]);
            a[1][s][2] = __float_as_uint(sX[r0b * XP + k0 + 4]);
            a[1][s][3] = __float_as_uint(sX[(r0b + 8) * XP + k0 + 4]);
        }
        #pragma unroll
        for (int j = 0; j < 8; j++) {
            uint4 b = __ldg(&gW[((wn * 8 + j) * 8 + kp) * 32 + lane]);
            mma8(d[0][j], a[0][0], b.x, b.y);
            mma8(d[1][j], a[1][0], b.x, b.y);
            mma8(d[0][j], a[0][1], b.z, b.w);
            mma8(d[1][j], a[1][1], b.z, b.w);
        }
    }
}

// ---- 512-thread (16 warp, 4m x 4n) product: 32-col slab, d[2][4][4] ----
__device__ __forceinline__ void product4(const float* sX, const uint4* __restrict__ gW,
                                         float d[2][4][4], int wm, int wn, int lane) {
    int r0a = wm * 32 + 0  + (lane >> 2);
    int r0b = wm * 32 + 16 + (lane >> 2);
    int kl = lane & 3;
    for (int kp = 0; kp < 8; kp++) {
        uint32_t a[2][2][4];
        #pragma unroll
        for (int s = 0; s < 2; s++) {
            int k0 = (kp * 2 + s) * 8 + kl;
            a[0][s][0] = __float_as_uint(sX[r0a * XP + k0]);
            a[0][s][1] = __float_as_uint(sX[(r0a + 8) * XP + k0]);
            a[0][s][2] = __float_as_uint(sX[r0a * XP + k0 + 4]);
            a[0][s][3] = __float_as_uint(sX[(r0a + 8) * XP + k0 + 4]);
            a[1][s][0] = __float_as_uint(sX[r0b * XP + k0]);
            a[1][s][1] = __float_as_uint(sX[(r0b + 8) * XP + k0]);
            a[1][s][2] = __float_as_uint(sX[r0b * XP + k0 + 4]);
            a[1][s][3] = __float_as_uint(sX[(r0b + 8) * XP + k0 + 4]);
        }
        #pragma unroll
        for (int j = 0; j < 4; j++) {
            uint4 b = __ldg(&gW[((wn * 4 + j) * 8 + kp) * 32 + lane]);
            mma8(d[0][j], a[0][0], b.x, b.y);
            mma8(d[1][j], a[1][0], b.x, b.y);
            mma8(d[0][j], a[0][1], b.z, b.w);
            mma8(d[1][j], a[1][1], b.z, b.w);
        }
    }
}

// p = sigmoid(fdst@wr + h@ur + br) * h  -> bf16 g_pb
__global__ void __launch_bounds__(256, 2) k_gemmB(const float* __restrict__ fdst,
                                                  const float* __restrict__ h,
                                                  const float* __restrict__ br, int n) {
    extern __shared__ char sm[];
    float* sX = (float*)sm;
    int tid = threadIdx.x, w = tid >> 5, lane = tid & 31;
    int wm = w >> 1, wn = w & 1;
    int rowBase = blockIdx.x * 128;

    load_xT<256>(sX, fdst, rowBase, n, tid);
    __syncthreads();

    float d[2][8][4];
    #pragma unroll
    for (int i = 0; i < 2; i++)
        #pragma unroll
        for (int j = 0; j < 8; j++)
            #pragma unroll
            for (int q = 0; q < 4; q++) d[i][j][q] = 0.f;

    product8(sX, &g_wimg[2 * 4096], d, wm, wn, lane);
    __syncthreads();
    load_xT<256>(sX, h, rowBase, n, tid);
    __syncthreads();
    product8(sX, &g_wimg[3 * 4096], d, wm, wn, lane);

    #pragma unroll
    for (int i = 0; i < 2; i++) {
        int Rl = (wm * 2 + i) * 16 + (lane >> 2);
        int R = rowBase + Rl;
        #pragma unroll
        for (int j = 0; j < 8; j++) {
            int C = wn * 64 + j * 8 + (lane & 3) * 2;
            float b0 = br[C], b1 = br[C + 1];
            if (R < n) {
                float h0 = sX[Rl * XP + C], h1 = sX[Rl * XP + C + 1];
                g_pb[(size_t)R * 64 + (C >> 1)] =
                    __floats2bfloat162_rn(sigmoidf(d[i][j][0] + b0) * h0,
                                          sigmoidf(d[i][j][1] + b1) * h1);
            }
            if (R + 8 < n) {
                float h0 = sX[(Rl + 8) * XP + C], h1 = sX[(Rl + 8) * XP + C + 1];
                g_pb[(size_t)(R + 8) * 64 + (C >> 1)] =
                    __floats2bfloat162_rn(sigmoidf(d[i][j][2] + b0) * h0,
                                          sigmoidf(d[i][j][3] + b1) * h1);
            }
        }
    }
}

// zp = fsrc@wz + bz ; cp = fsrc@w + b   (independent of everything else)
__global__ void __launch_bounds__(256, 2) k_gemmA(const float* __restrict__ fsrc,
                                                  const float* __restrict__ bz,
                                                  const float* __restrict__ b, int n) {
    extern __shared__ char sm[];
    float* sX = (float*)sm;
    int tid = threadIdx.x, w = tid >> 5, lane = tid & 31;
    int wm = w >> 1, wn = w & 1;
    int rowBase = blockIdx.x * 128;

    load_xT<256>(sX, fsrc, rowBase, n, tid);
    __syncthreads();

    for (int which = 0; which < 2; which++) {
        float d[2][8][4];
        #pragma unroll
        for (int i = 0; i < 2; i++)
            #pragma unroll
            for (int j = 0; j < 8; j++)
                #pragma unroll
                for (int q = 0; q < 4; q++) d[i][j][q] = 0.f;
        product8(sX, &g_wimg[which * 4096], d, wm, wn, lane);
        const float* bias = which ? b : bz;
        float* outp = which ? g_cp : g_zp;
        #pragma unroll
        for (int i = 0; i < 2; i++) {
            int R = rowBase + (wm * 2 + i) * 16 + (lane >> 2);
            #pragma unroll
            for (int j = 0; j < 8; j++) {
                int C = wn * 64 + j * 8 + (lane & 3) * 2;
                float b0 = bias[C], b1 = bias[C + 1];
                if (R < n)
                    *(float2*)(outp + (size_t)R * 128 + C) =
                        make_float2(d[i][j][0] + b0, d[i][j][1] + b1);
                if (R + 8 < n)
                    *(float2*)(outp + (size_t)(R + 8) * 128 + C) =
                        make_float2(d[i][j][2] + b0, d[i][j][3] + b1);
            }
        }
    }
}

// z = sigmoid(zp + s@uz); ht = tanh(cp + q@u); out = (1-z)*s + z*ht
__global__ void __launch_bounds__(512, 1) k_gemmC(float* __restrict__ out, int n) {
    extern __shared__ char sm[];
    float* sS = (float*)sm;                    // s tile, persistent
    float* sX = (float*)(sm + 128 * XP * 4);   // q tile
    int tid = threadIdx.x, w = tid >> 5, lane = tid & 31;
    int wm = w >> 2, wn = w & 3;
    int rowBase = blockIdx.x * 128;

    load_xT<512>(sS, g_s, rowBase, n, tid);
    load_xT<512>(sX, g_q, rowBase, n, tid);
    __syncthreads();

    float d1[2][4][4], d2[2][4][4];
    #pragma unroll
    for (int i = 0; i < 2; i++)
        #pragma unroll
        for (int j = 0; j < 4; j++)
            #pragma unroll
            for (int q = 0; q < 4; q++) { d1[i][j][q] = 0.f; d2[i][j][q] = 0.f; }

    product4(sS, &g_wimg[4 * 4096], d1, wm, wn, lane);   // s @ uz
    product4(sX, &g_wimg[5 * 4096], d2, wm, wn, lane);   // q @ u

    #pragma unroll
    for (int i = 0; i < 2; i++) {
        int Rl = wm * 32 + i * 16 + (lane >> 2);
        int R = rowBase + Rl;
        #pragma unroll
        for (int j = 0; j < 4; j++) {
            int C = wn * 32 + j * 8 + (lane & 3) * 2;
            if (R < n) {
                float2 zp = *(const float2*)(g_zp + (size_t)R * 128 + C);
                float2 cp = *(const float2*)(g_cp + (size_t)R * 128 + C);
                float s0 = sS[Rl * XP + C], s1 = sS[Rl * XP + C + 1];
                float z0 = sigmoidf(zp.x + d1[i][j][0]);
                float z1 = sigmoidf(zp.y + d1[i][j][1]);
                float t0 = tanh_fast(cp.x + d2[i][j][0]);
                float t1 = tanh_fast(cp.y + d2[i][j][1]);
                *(float2*)(out + (size_t)R * 128 + C) =
                    make_float2((1.f - z0) * s0 + z0 * t0,
                                (1.f - z1) * s1 + z1 * t1);
            }
            if (R + 8 < n) {
                float2 zp = *(const float2*)(g_zp + (size_t)(R + 8) * 128 + C);
                float2 cp = *(const float2*)(g_cp + (size_t)(R + 8) * 128 + C);
                float s0 = sS[(Rl + 8) * XP + C], s1 = sS[(Rl + 8) * XP + C + 1];
                float z0 = sigmoidf(zp.x + d1[i][j][2]);
                float z1 = sigmoidf(zp.y + d1[i][j][3]);
                float t0 = tanh_fast(cp.x + d2[i][j][2]);
                float t1 = tanh_fast(cp.y + d2[i][j][3]);
                *(float2*)(out + (size_t)(R + 8) * 128 + C) =
                    make_float2((1.f - z0) * s0 + z0 * t0,
                                (1.f - z1) * s1 + z1 * t1);
            }
        }
    }
}

// ---------------- launch ----------------
extern "C" void kernel_launch(void* const* d_in, const int* in_sizes, int n_in,
                              void* d_out, int out_size)
{
    const float* h    = (const float*)d_in[0];
    const float* fsrc = (const float*)d_in[1];
    const float* fdst = (const float*)d_in[2];
    const int*   src  = (const int*)d_in[3];
    const int*   dst  = (const int*)d_in[4];
    const float* wz   = (const float*)d_in[5];
    const float* uz   = (const float*)d_in[6];
    const float* bz   = (const float*)d_in[7];
    const float* wr   = (const float*)d_in[8];
    const float* ur   = (const float*)d_in[9];
    const float* br   = (const float*)d_in[10];
    const float* w    = (const float*)d_in[11];
    const float* u    = (const float*)d_in[12];
    const float* b    = (const float*)d_in[13];
    float* out = (float*)d_out;

    int n = in_sizes[0] / 128;
    int e = in_sizes[3];
    if (n > NMAX || e > EMAX) return;

    static cudaStream_t sB = nullptr, sC = nullptr;
    static cudaEvent_t evF = nullptr, evCSR = nullptr, evQ = nullptr, evA = nullptr;
    if (!sB) {
        cudaStreamCreateWithFlags(&sB, cudaStreamNonBlocking);
        cudaStreamCreateWithFlags(&sC, cudaStreamNonBlocking);
        cudaEventCreateWithFlags(&evF, cudaEventDisableTiming);
        cudaEventCreateWithFlags(&evCSR, cudaEventDisableTiming);
        cudaEventCreateWithFlags(&evQ, cudaEventDisableTiming);
        cudaEventCreateWithFlags(&evA, cudaEventDisableTiming);
    }

    cudaFuncSetAttribute(k_gemmB, cudaFuncAttributeMaxDynamicSharedMemorySize, SM_B);
    cudaFuncSetAttribute(k_gemmA, cudaFuncAttributeMaxDynamicSharedMemorySize, SM_B);
    cudaFuncSetAttribute(k_gemmC, cudaFuncAttributeMaxDynamicSharedMemorySize, SM_C);

    int gemmBlocks = (n + 127) / 128;
    int nb = (n + 1023) / 1024;

    // prep first (gemmA and gemmB both need weight images), then 3-way fork
    k_prep<<<dim3(16, 6), 256>>>(wz, w, wr, ur, uz, u);
    cudaEventRecord(evF, 0);
    cudaStreamWaitEvent(sB, evF, 0);
    cudaStreamWaitEvent(sC, evF, 0);

    // stream C: fsrc gate pre-activations (depends on nothing but fsrc+weights)
    k_gemmA<<<gemmBlocks, 256, SM_B, sC>>>(fsrc, bz, b, n);
    cudaEventRecord(evA, sC);

    // stream B: gemmB
    k_gemmB<<<gemmBlocks, 256, SM_B, sB>>>(fdst, h, br, n);

    // main: fused h-compress+zero, then CSR chain
    k_hzero<<<(n * 32 + 255) / 256, 256>>>(h, n);
    k_hist<<<(e + 255) / 256, 256>>>(dst, e);
    k_part<<<nb, 1024>>>(n);
    k_scanb<<<1, 128>>>(nb);
    k_add<<<(n + 1023) / 1024, 1024>>>(n, e);
    k_scatter<<<(e + 255) / 256, 256>>>(src, dst, e);
    cudaEventRecord(evCSR, 0);

    // s-reduce on main
    k_reduceS<<<(n + 7) / 8, 256>>>(n);

    // q-reduce on stream B after CSR + gemmB
    cudaStreamWaitEvent(sB, evCSR, 0);
    k_reduceQ<<<(n + 7) / 8, 256, 0, sB>>>(n);
    cudaEventRecord(evQ, sB);

    // join all, final gate GEMM + epilogue
    cudaStreamWaitEvent(0, evQ, 0);
    cudaStreamWaitEvent(0, evA, 0);
    k_gemmC<<<gemmBlocks, 512, SM_C>>>(out, n);
}

// round 15
// speedup vs baseline: 1.1547x; 1.1547x over previous
#include <cuda_runtime.h>
#include <cuda_bf16.h>
#include <cuda_fp16.h>
#include <cstdint>

#define NMAX 100000
#define EMAX 1600000

// ---------------- scratch ----------------
__device__ __nv_bfloat162 g_pb[NMAX * 64];   // p compressed to bf16 (gather operand)
__device__ __half2 g_hh[NMAX * 64];          // h compressed to fp16 (gather operand)
__device__ float g_s [NMAX * 128];
__device__ float g_q [NMAX * 128];
__device__ int   g_cnt[NMAX];
__device__ int   g_off[NMAX + 1];
__device__ int   g_cur[NMAX];
__device__ int   g_perm[EMAX];
__device__ int   g_bsum[128];
__device__ int   g_bpre[128];
__device__ uint4 g_wimg[6 * 2048];   // 6 bf16 weight images, 32KB each, B-fragment order

__device__ __forceinline__ float sigmoidf(float x) { return 1.0f / (1.0f + __expf(-x)); }
__device__ __forceinline__ float tanh_fast(float x) {
    return __fdividef(2.0f, 1.0f + __expf(-2.0f * x)) - 1.0f;
}
__device__ __forceinline__ uint32_t pk(float lo, float hi) {
    __nv_bfloat162 h = __floats2bfloat162_rn(lo, hi);   // .x = lo (low half)
    return *(uint32_t*)&h;
}

// ---------------- mma.sync m16n8k16 bf16 ----------------
__device__ __forceinline__ void mma16(float* d, const uint32_t* a, uint32_t b0, uint32_t b1) {
    asm("mma.sync.aligned.m16n8k16.row.col.f32.bf16.bf16.f32 "
        "{%0,%1,%2,%3},{%4,%5,%6,%7},{%8,%9},{%0,%1,%2,%3};"
        : "+f"(d[0]), "+f"(d[1]), "+f"(d[2]), "+f"(d[3])
        : "r"(a[0]), "r"(a[1]), "r"(a[2]), "r"(a[3]), "r"(b0), "r"(b1));
}

// ---------------- fused: h -> fp16 compression + counter zero ----------------
__global__ void k_hzero(const float* __restrict__ h, int n) {
    int i = blockIdx.x * blockDim.x + threadIdx.x;
    if (i < n * 32) {
        float4 v = ((const float4*)h)[i];
        g_hh[i * 2 + 0] = __floats2half2_rn(v.x, v.y);
        g_hh[i * 2 + 1] = __floats2half2_rn(v.z, v.w);
    }
    if (i < n) g_cnt[i] = 0;
}

// ---------------- CSR build ----------------
__global__ void k_hist(const int* __restrict__ dst, int e) {
    int i = blockIdx.x * blockDim.x + threadIdx.x;
    if (i < e) atomicAdd(&g_cnt[dst[i]], 1);
}

__global__ void k_part(int n) {
    __shared__ int sm[1024];
    int b = blockIdx.x, t = threadIdx.x;
    int idx = b * 1024 + t;
    int v = (idx < n) ? g_cnt[idx] : 0;
    sm[t] = v;
    __syncthreads();
    #pragma unroll
    for (int off = 1; off < 1024; off <<= 1) {
        int x = (t >= off) ? sm[t - off] : 0;
        __syncthreads();
        sm[t] += x;
        __syncthreads();
    }
    if (idx < n) g_off[idx] = sm[t] - v;
    if (t == 1023) g_bsum[b] = sm[t];
}

__global__ void k_scanb(int nb) {
    __shared__ int sm[128];
    int t = threadIdx.x;
    int v = (t < nb) ? g_bsum[t] : 0;
    sm[t] = v;
    __syncthreads();
    #pragma unroll
    for (int off = 1; off < 128; off <<= 1) {
        int x = (t >= off) ? sm[t - off] : 0;
        __syncthreads();
        sm[t] += x;
        __syncthreads();
    }
    if (t < nb) g_bpre[t] = sm[t] - v;
}

__global__ void k_add(int n, int e) {
    int idx = blockIdx.x * blockDim.x + threadIdx.x;
    if (idx < n) {
        int o = g_off[idx] + g_bpre[idx >> 10];
        g_off[idx] = o;
        g_cur[idx] = o;
    }
    if (idx == 0) g_off[n] = e;
}

__global__ void k_scatter(const int* __restrict__ src, const int* __restrict__ dst, int e) {
    int i = blockIdx.x * blockDim.x + threadIdx.x;
    if (i < e) {
        int d = dst[i];
        int pos = atomicAdd(&g_cur[d], 1);
        g_perm[pos] = src[i];
    }
}

// ---------------- segment reduce, split, 8-deep gather pipeline ----------------
__global__ void k_reduceS(int n) {
    int gw = (blockIdx.x * blockDim.x + threadIdx.x) >> 5;
    int lane = threadIdx.x & 31;
    if (gw >= n) return;
    int i0 = g_off[gw], i1 = g_off[gw + 1];
    const uint2* hh = (const uint2*)g_hh;
    float4 sa = make_float4(0.f, 0.f, 0.f, 0.f);
    int i = i0;
    for (; i + 7 < i1; i += 8) {
        uint2 b[8];
        #pragma unroll
        for (int k = 0; k < 8; k++) b[k] = hh[g_perm[i + k] * 32 + lane];
        #pragma unroll
        for (int k = 0; k < 8; k++) {
            float2 f = __half22float2(*(__half2*)&b[k].x);
            float2 g = __half22float2(*(__half2*)&b[k].y);
            sa.x += f.x; sa.y += f.y; sa.z += g.x; sa.w += g.y;
        }
    }
    for (; i + 3 < i1; i += 4) {
        uint2 b[4];
        #pragma unroll
        for (int k = 0; k < 4; k++) b[k] = hh[g_perm[i + k] * 32 + lane];
        #pragma unroll
        for (int k = 0; k < 4; k++) {
            float2 f = __half22float2(*(__half2*)&b[k].x);
            float2 g = __half22float2(*(__half2*)&b[k].y);
            sa.x += f.x; sa.y += f.y; sa.z += g.x; sa.w += g.y;
        }
    }
    for (; i < i1; i++) {
        uint2 b0 = hh[g_perm[i] * 32 + lane];
        float2 f = __half22float2(*(__half2*)&b0.x);
        float2 g = __half22float2(*(__half2*)&b0.y);
        sa.x += f.x; sa.y += f.y; sa.z += g.x; sa.w += g.y;
    }
    ((float4*)g_s)[gw * 32 + lane] = sa;
}

__global__ void k_reduceQ(int n) {
    int gw = (blockIdx.x * blockDim.x + threadIdx.x) >> 5;
    int lane = threadIdx.x & 31;
    if (gw >= n) return;
    int i0 = g_off[gw], i1 = g_off[gw + 1];
    const uint2* pb = (const uint2*)g_pb;
    float4 qa = make_float4(0.f, 0.f, 0.f, 0.f);
    int i = i0;
    for (; i + 7 < i1; i += 8) {
        uint2 b[8];
        #pragma unroll
        for (int k = 0; k < 8; k++) b[k] = pb[g_perm[i + k] * 32 + lane];
        #pragma unroll
        for (int k = 0; k < 8; k++) {
            float2 f = __bfloat1622float2(*(__nv_bfloat162*)&b[k].x);
            float2 g = __bfloat1622float2(*(__nv_bfloat162*)&b[k].y);
            qa.x += f.x; qa.y += f.y; qa.z += g.x; qa.w += g.y;
        }
    }
    for (; i + 3 < i1; i += 4) {
        uint2 b[4];
        #pragma unroll
        for (int k = 0; k < 4; k++) b[k] = pb[g_perm[i + k] * 32 + lane];
        #pragma unroll
        for (int k = 0; k < 4; k++) {
            float2 f = __bfloat1622float2(*(__nv_bfloat162*)&b[k].x);
            float2 g = __bfloat1622float2(*(__nv_bfloat162*)&b[k].y);
            qa.x += f.x; qa.y += f.y; qa.z += g.x; qa.w += g.y;
        }
    }
    for (; i < i1; i++) {
        uint2 b0 = pb[g_perm[i] * 32 + lane];
        float2 f = __bfloat1622float2(*(__nv_bfloat162*)&b0.x);
        float2 g = __bfloat1622float2(*(__nv_bfloat162*)&b0.y);
        qa.x += f.x; qa.y += f.y; qa.z += g.x; qa.w += g.y;
    }
    ((float4*)g_q)[gw * 32 + lane] = qa;
}

// ---------------- bf16 weight fragment image prep ----------------
// W[k][n] row-major. uint4 t = (nt*4 + kp)*32 + lane covers ksteps 2kp,2kp+1:
//   n = nt*8 + lane>>2 ; kb = kp*32 + (lane&3)*2
//   v = { pk(W[kb],W[kb+1]), pk(W[kb+8],W[kb+9]),
//         pk(W[kb+16],W[kb+17]), pk(W[kb+24],W[kb+25]) }   (all at column n)
__global__ void k_prep(const float* w0, const float* w1, const float* w2,
                       const float* w3, const float* w4, const float* w5) {
    int mat = blockIdx.y;
    int t = blockIdx.x * 256 + threadIdx.x;    // 0..2047 per matrix
    if (t >= 2048) return;
    const float* srcs[6] = {w0, w1, w2, w3, w4, w5};
    const float* W = srcs[mat];
    int nt = t >> 7, kp = (t >> 5) & 3, lane = t & 31;
    int n = nt * 8 + (lane >> 2);
    int kb = kp * 32 + (lane & 3) * 2;
    uint4 v;
    v.x = pk(W[(kb + 0)  * 128 + n], W[(kb + 1)  * 128 + n]);
    v.y = pk(W[(kb + 8)  * 128 + n], W[(kb + 9)  * 128 + n]);
    v.z = pk(W[(kb + 16) * 128 + n], W[(kb + 17) * 128 + n]);
    v.w = pk(W[(kb + 24) * 128 + n], W[(kb + 25) * 128 + n]);
    g_wimg[mat * 2048 + t] = v;
}

// ---------------- GEMM layouts ----------------
#define XP    132
#define SM_B  (128 * XP * 4)        // 67584 (gemmB, 256 thr, 2 blocks/SM)
#define SM_AC (2 * 128 * XP * 4)    // 135168 (gemmAC, 512 thr, 1 block/SM)

// plain fp32 x tile (full precision kept for epilogues)
template<int NT>
__device__ __forceinline__ void load_xT(float* sX, const float* __restrict__ x,
                                        int rowBase, int n, int tid) {
    const float4* s4 = (const float4*)x;
    #pragma unroll 4
    for (int i = tid; i < 4096; i += NT) {
        int m = i >> 5, c4 = i & 31;
        float4 v = (rowBase + m < n) ? s4[(size_t)(rowBase + m) * 32 + c4]
                                     : make_float4(0.f, 0.f, 0.f, 0.f);
        *(float4*)(&sX[m * XP + c4 * 4]) = v;
    }
}

// build one m16 A-fragment (4 regs) for kstep offset kof from fp32 smem
__device__ __forceinline__ void loadA(const float* sX, int row, int kof, uint32_t a[4]) {
    float2 p0 = *(const float2*)&sX[row * XP + kof];
    float2 p1 = *(const float2*)&sX[(row + 8) * XP + kof];
    float2 p2 = *(const float2*)&sX[row * XP + kof + 8];
    float2 p3 = *(const float2*)&sX[(row + 8) * XP + kof + 8];
    a[0] = pk(p0.x, p0.y);
    a[1] = pk(p1.x, p1.y);
    a[2] = pk(p2.x, p2.y);
    a[3] = pk(p3.x, p3.y);
}

// ---- 256-thread (8 warp, 2(wn) x 4(wm)) product: 64-col slab, d[2][8][4] ----
__device__ __forceinline__ void product8(const float* sX, const uint4* __restrict__ gW,
                                         float d[2][8][4], int wm, int wn, int lane) {
    int r0a = (wm * 2 + 0) * 16 + (lane >> 2);
    int r0b = (wm * 2 + 1) * 16 + (lane >> 2);
    int kl = lane & 3;
    for (int kp = 0; kp < 4; kp++) {
        int kof0 = kp * 32 + kl * 2;
        int kof1 = kof0 + 16;
        uint32_t a0[2][4], a1[2][4];
        loadA(sX, r0a, kof0, a0[0]); loadA(sX, r0b, kof0, a0[1]);
        loadA(sX, r0a, kof1, a1[0]); loadA(sX, r0b, kof1, a1[1]);
        #pragma unroll
        for (int j = 0; j < 8; j++) {
            uint4 b = __ldg(&gW[((wn * 8 + j) * 4 + kp) * 32 + lane]);
            mma16(d[0][j], a0[0], b.x, b.y);
            mma16(d[1][j], a0[1], b.x, b.y);
            mma16(d[0][j], a1[0], b.z, b.w);
            mma16(d[1][j], a1[1], b.z, b.w);
        }
    }
}

// ---- 512-thread (16 warp, 4m x 4n) product: 32-col slab, d[2][4][4] ----
__device__ __forceinline__ void product4(const float* sX, const uint4* __restrict__ gW,
                                         float d[2][4][4], int wm, int wn, int lane) {
    int r0a = wm * 32 + 0  + (lane >> 2);
    int r0b = wm * 32 + 16 + (lane >> 2);
    int kl = lane & 3;
    for (int kp = 0; kp < 4; kp++) {
        int kof0 = kp * 32 + kl * 2;
        int kof1 = kof0 + 16;
        uint32_t a0[2][4], a1[2][4];
        loadA(sX, r0a, kof0, a0[0]); loadA(sX, r0b, kof0, a0[1]);
        loadA(sX, r0a, kof1, a1[0]); loadA(sX, r0b, kof1, a1[1]);
        #pragma unroll
        for (int j = 0; j < 4; j++) {
            uint4 b = __ldg(&gW[((wn * 4 + j) * 4 + kp) * 32 + lane]);
            mma16(d[0][j], a0[0], b.x, b.y);
            mma16(d[1][j], a0[1], b.x, b.y);
            mma16(d[0][j], a1[0], b.z, b.w);
            mma16(d[1][j], a1[1], b.z, b.w);
        }
    }
}

// p = sigmoid(fdst@wr + h@ur + br) * h  -> bf16 g_pb
__global__ void __launch_bounds__(256, 2) k_gemmB(const float* __restrict__ fdst,
                                                  const float* __restrict__ h,
                                                  const float* __restrict__ br, int n) {
    extern __shared__ char sm[];
    float* sX = (float*)sm;
    int tid = threadIdx.x, w = tid >> 5, lane = tid & 31;
    int wm = w >> 1, wn = w & 1;
    int rowBase = blockIdx.x * 128;

    load_xT<256>(sX, fdst, rowBase, n, tid);
    __syncthreads();

    float d[2][8][4];
    #pragma unroll
    for (int i = 0; i < 2; i++)
        #pragma unroll
        for (int j = 0; j < 8; j++)
            #pragma unroll
            for (int q = 0; q < 4; q++) d[i][j][q] = 0.f;

    product8(sX, &g_wimg[2 * 2048], d, wm, wn, lane);
    __syncthreads();
    load_xT<256>(sX, h, rowBase, n, tid);
    __syncthreads();
    product8(sX, &g_wimg[3 * 2048], d, wm, wn, lane);

    #pragma unroll
    for (int i = 0; i < 2; i++) {
        int Rl = (wm * 2 + i) * 16 + (lane >> 2);
        int R = rowBase + Rl;
        #pragma unroll
        for (int j = 0; j < 8; j++) {
            int C = wn * 64 + j * 8 + (lane & 3) * 2;
            float b0 = br[C], b1 = br[C + 1];
            if (R < n) {
                float h0 = sX[Rl * XP + C], h1 = sX[Rl * XP + C + 1];
                g_pb[(size_t)R * 64 + (C >> 1)] =
                    __floats2bfloat162_rn(sigmoidf(d[i][j][0] + b0) * h0,
                                          sigmoidf(d[i][j][1] + b1) * h1);
            }
            if (R + 8 < n) {
                float h0 = sX[(Rl + 8) * XP + C], h1 = sX[(Rl + 8) * XP + C + 1];
                g_pb[(size_t)(R + 8) * 64 + (C >> 1)] =
                    __floats2bfloat162_rn(sigmoidf(d[i][j][2] + b0) * h0,
                                          sigmoidf(d[i][j][3] + b1) * h1);
            }
        }
    }
}

// fused: z = sigmoid(fsrc@wz + s@uz + bz); ht = tanh(fsrc@w + q@u + b);
//        out = (1-z)*s + z*ht     (s kept fp32 in smem for epilogue)
__global__ void __launch_bounds__(512, 1) k_gemmAC(const float* __restrict__ fsrc,
                                                   const float* __restrict__ bz,
                                                   const float* __restrict__ b,
                                                   float* __restrict__ out, int n) {
    extern __shared__ char sm[];
    float* sS = (float*)sm;                    // s tile (fp32), persistent
    float* sX = (float*)(sm + 128 * XP * 4);   // q tile, then fsrc tile
    int tid = threadIdx.x, w = tid >> 5, lane = tid & 31;
    int wm = w >> 2, wn = w & 3;
    int rowBase = blockIdx.x * 128;

    load_xT<512>(sS, g_s, rowBase, n, tid);
    load_xT<512>(sX, g_q, rowBase, n, tid);
    __syncthreads();

    float d1[2][4][4], d2[2][4][4];
    #pragma unroll
    for (int i = 0; i < 2; i++)
        #pragma unroll
        for (int j = 0; j < 4; j++)
            #pragma unroll
            for (int q = 0; q < 4; q++) { d1[i][j][q] = 0.f; d2[i][j][q] = 0.f; }

    product4(sS, &g_wimg[4 * 2048], d1, wm, wn, lane);   // s @ uz
    product4(sX, &g_wimg[5 * 2048], d2, wm, wn, lane);   // q @ u
    __syncthreads();
    load_xT<512>(sX, fsrc, rowBase, n, tid);
    __syncthreads();
    product4(sX, &g_wimg[0 * 2048], d1, wm, wn, lane);   // + fsrc @ wz
    product4(sX, &g_wimg[1 * 2048], d2, wm, wn, lane);   // + fsrc @ w

    #pragma unroll
    for (int i = 0; i < 2; i++) {
        int Rl = wm * 32 + i * 16 + (lane >> 2);
        int R = rowBase + Rl;
        #pragma unroll
        for (int j = 0; j < 4; j++) {
            int C = wn * 32 + j * 8 + (lane & 3) * 2;
            float bz0 = bz[C], bz1 = bz[C + 1];
            float bb0 = b[C],  bb1 = b[C + 1];
            if (R < n) {
                float s0 = sS[Rl * XP + C], s1 = sS[Rl * XP + C + 1];
                float z0 = sigmoidf(d1[i][j][0] + bz0);
                float z1 = sigmoidf(d1[i][j][1] + bz1);
                float t0 = tanh_fast(d2[i][j][0] + bb0);
                float t1 = tanh_fast(d2[i][j][1] + bb1);
                *(float2*)(out + (size_t)R * 128 + C) =
                    make_float2((1.f - z0) * s0 + z0 * t0,
                                (1.f - z1) * s1 + z1 * t1);
            }
            if (R + 8 < n) {
                float s0 = sS[(Rl + 8) * XP + C], s1 = sS[(Rl + 8) * XP + C + 1];
                float z0 = sigmoidf(d1[i][j][2] + bz0);
                float z1 = sigmoidf(d1[i][j][3] + bz1);
                float t0 = tanh_fast(d2[i][j][2] + bb0);
                float t1 = tanh_fast(d2[i][j][3] + bb1);
                *(float2*)(out + (size_t)(R + 8) * 128 + C) =
                    make_float2((1.f - z0) * s0 + z0 * t0,
                                (1.f - z1) * s1 + z1 * t1);
            }
        }
    }
}

// ---------------- launch ----------------
extern "C" void kernel_launch(void* const* d_in, const int* in_sizes, int n_in,
                              void* d_out, int out_size)
{
    const float* h    = (const float*)d_in[0];
    const float* fsrc = (const float*)d_in[1];
    const float* fdst = (const float*)d_in[2];
    const int*   src  = (const int*)d_in[3];
    const int*   dst  = (const int*)d_in[4];
    const float* wz   = (const float*)d_in[5];
    const float* uz   = (const float*)d_in[6];
    const float* bz   = (const float*)d_in[7];
    const float* wr   = (const float*)d_in[8];
    const float* ur   = (const float*)d_in[9];
    const float* br   = (const float*)d_in[10];
    const float* w    = (const float*)d_in[11];
    const float* u    = (const float*)d_in[12];
    const float* b    = (const float*)d_in[13];
    float* out = (float*)d_out;

    int n = in_sizes[0] / 128;
    int e = in_sizes[3];
    if (n > NMAX || e > EMAX) return;

    static cudaStream_t sB = nullptr;
    static cudaEvent_t evF = nullptr, evCSR = nullptr, evQ = nullptr;
    if (!sB) {
        cudaStreamCreateWithFlags(&sB, cudaStreamNonBlocking);
        cudaEventCreateWithFlags(&evF, cudaEventDisableTiming);
        cudaEventCreateWithFlags(&evCSR, cudaEventDisableTiming);
        cudaEventCreateWithFlags(&evQ, cudaEventDisableTiming);
    }

    cudaFuncSetAttribute(k_gemmB,  cudaFuncAttributeMaxDynamicSharedMemorySize, SM_B);
    cudaFuncSetAttribute(k_gemmAC, cudaFuncAttributeMaxDynamicSharedMemorySize, SM_AC);

    int gemmBlocks = (n + 127) / 128;
    int nb = (n + 1023) / 1024;

    // fork: branch B (prep + gemmB) runs concurrently with the CSR chain
    cudaEventRecord(evF, 0);
    cudaStreamWaitEvent(sB, evF, 0);
    k_prep<<<dim3(8, 6), 256, 0, sB>>>(wz, w, wr, ur, uz, u);
    k_gemmB<<<gemmBlocks, 256, SM_B, sB>>>(fdst, h, br, n);

    // branch A: fused h-compress+zero, then CSR chain on main stream
    k_hzero<<<(n * 32 + 255) / 256, 256>>>(h, n);
    k_hist<<<(e + 255) / 256, 256>>>(dst, e);
    k_part<<<nb, 1024>>>(n);
    k_scanb<<<1, 128>>>(nb);
    k_add<<<(n + 1023) / 1024, 1024>>>(n, e);
    k_scatter<<<(e + 255) / 256, 256>>>(src, dst, e);
    cudaEventRecord(evCSR, 0);

    // s-reduce needs only CSR + compressed h: run immediately on main stream
    k_reduceS<<<(n + 7) / 8, 256>>>(n);

    // q-reduce needs CSR + gemmB output: run on stream B
    cudaStreamWaitEvent(sB, evCSR, 0);
    k_reduceQ<<<(n + 7) / 8, 256, 0, sB>>>(n);
    cudaEventRecord(evQ, sB);

    // join, then fused gate GEMM
    cudaStreamWaitEvent(0, evQ, 0);
    k_gemmAC<<<gemmBlocks, 512, SM_AC>>>(fsrc, bz, b, out, n);
}

// round 16
// speedup vs baseline: 1.2226x; 1.0588x over previous
#include <cuda_runtime.h>
#include <cuda_bf16.h>
#include <cuda_fp16.h>
#include <cstdint>

#define NMAX 100000
#define EMAX 1600000

// ---------------- scratch ----------------
__device__ __nv_bfloat162 g_pb[NMAX * 64];   // p compressed to bf16 (gather operand)
__device__ __half2 g_hh[NMAX * 64];          // h compressed to fp16 (gather operand)
__device__ float g_s [NMAX * 128];
__device__ float g_q [NMAX * 128];
__device__ int   g_cnt[NMAX];                // invariant: zero at kernel_launch entry
__device__ int   g_off[NMAX + 1];
__device__ int   g_cur[NMAX];
__device__ int   g_perm[EMAX];
__device__ int   g_bsum[128];
__device__ int   g_bpre[128];
__device__ uint4 g_wimg[6 * 2048];   // 6 bf16 weight images, 32KB each, B-fragment order

__device__ __forceinline__ float sigmoidf(float x) { return 1.0f / (1.0f + __expf(-x)); }
__device__ __forceinline__ float tanh_fast(float x) {
    return __fdividef(2.0f, 1.0f + __expf(-2.0f * x)) - 1.0f;
}
__device__ __forceinline__ uint32_t pk(float lo, float hi) {
    __nv_bfloat162 h = __floats2bfloat162_rn(lo, hi);   // .x = lo (low half)
    return *(uint32_t*)&h;
}

// ---------------- mma.sync m16n8k16 bf16 ----------------
__device__ __forceinline__ void mma16(float* d, const uint32_t* a, uint32_t b0, uint32_t b1) {
    asm("mma.sync.aligned.m16n8k16.row.col.f32.bf16.bf16.f32 "
        "{%0,%1,%2,%3},{%4,%5,%6,%7},{%8,%9},{%0,%1,%2,%3};"
        : "+f"(d[0]), "+f"(d[1]), "+f"(d[2]), "+f"(d[3])
        : "r"(a[0]), "r"(a[1]), "r"(a[2]), "r"(a[3]), "r"(b0), "r"(b1));
}

// ---------------- h -> fp16 compression (off critical path, stream C) ----------------
__global__ void k_hcomp(const float* __restrict__ h, int n) {
    int i = blockIdx.x * blockDim.x + threadIdx.x;
    if (i < n * 32) {
        float4 v = ((const float4*)h)[i];
        g_hh[i * 2 + 0] = __floats2half2_rn(v.x, v.y);
        g_hh[i * 2 + 1] = __floats2half2_rn(v.z, v.w);
    }
}

// ---------------- CSR build ----------------
__global__ void k_hist(const int* __restrict__ dst, int e) {
    int i = blockIdx.x * blockDim.x + threadIdx.x;
    if (i < e) atomicAdd(&g_cnt[dst[i]], 1);
}

// reads counts, zeroes them (restores entry invariant for the next replay)
__global__ void k_part(int n) {
    __shared__ int sm[1024];
    int b = blockIdx.x, t = threadIdx.x;
    int idx = b * 1024 + t;
    int v = 0;
    if (idx < n) { v = g_cnt[idx]; g_cnt[idx] = 0; }
    sm[t] = v;
    __syncthreads();
    #pragma unroll
    for (int off = 1; off < 1024; off <<= 1) {
        int x = (t >= off) ? sm[t - off] : 0;
        __syncthreads();
        sm[t] += x;
        __syncthreads();
    }
    if (idx < n) g_off[idx] = sm[t] - v;
    if (t == 1023) g_bsum[b] = sm[t];
}

__global__ void k_scanb(int nb) {
    __shared__ int sm[128];
    int t = threadIdx.x;
    int v = (t < nb) ? g_bsum[t] : 0;
    sm[t] = v;
    __syncthreads();
    #pragma unroll
    for (int off = 1; off < 128; off <<= 1) {
        int x = (t >= off) ? sm[t - off] : 0;
        __syncthreads();
        sm[t] += x;
        __syncthreads();
    }
    if (t < nb) g_bpre[t] = sm[t] - v;
}

__global__ void k_add(int n, int e) {
    int idx = blockIdx.x * blockDim.x + threadIdx.x;
    if (idx < n) {
        int o = g_off[idx] + g_bpre[idx >> 10];
        g_off[idx] = o;
        g_cur[idx] = o;
    }
    if (idx == 0) g_off[n] = e;
}

__global__ void k_scatter(const int* __restrict__ src, const int* __restrict__ dst, int e) {
    int i = blockIdx.x * blockDim.x + threadIdx.x;
    if (i < e) {
        int d = dst[i];
        int pos = atomicAdd(&g_cur[d], 1);
        g_perm[pos] = src[i];
    }
}

// ---------------- segment reduce, split, 8-deep gather pipeline ----------------
__global__ void k_reduceS(int n) {
    int gw = (blockIdx.x * blockDim.x + threadIdx.x) >> 5;
    int lane = threadIdx.x & 31;
    if (gw >= n) return;
    int i0 = g_off[gw], i1 = g_off[gw + 1];
    const uint2* hh = (const uint2*)g_hh;
    float4 sa = make_float4(0.f, 0.f, 0.f, 0.f);
    int i = i0;
    for (; i + 7 < i1; i += 8) {
        uint2 b[8];
        #pragma unroll
        for (int k = 0; k < 8; k++) b[k] = hh[g_perm[i + k] * 32 + lane];
        #pragma unroll
        for (int k = 0; k < 8; k++) {
            float2 f = __half22float2(*(__half2*)&b[k].x);
            float2 g = __half22float2(*(__half2*)&b[k].y);
            sa.x += f.x; sa.y += f.y; sa.z += g.x; sa.w += g.y;
        }
    }
    for (; i + 3 < i1; i += 4) {
        uint2 b[4];
        #pragma unroll
        for (int k = 0; k < 4; k++) b[k] = hh[g_perm[i + k] * 32 + lane];
        #pragma unroll
        for (int k = 0; k < 4; k++) {
            float2 f = __half22float2(*(__half2*)&b[k].x);
            float2 g = __half22float2(*(__half2*)&b[k].y);
            sa.x += f.x; sa.y += f.y; sa.z += g.x; sa.w += g.y;
        }
    }
    for (; i < i1; i++) {
        uint2 b0 = hh[g_perm[i] * 32 + lane];
        float2 f = __half22float2(*(__half2*)&b0.x);
        float2 g = __half22float2(*(__half2*)&b0.y);
        sa.x += f.x; sa.y += f.y; sa.z += g.x; sa.w += g.y;
    }
    ((float4*)g_s)[gw * 32 + lane] = sa;
}

__global__ void k_reduceQ(int n) {
    int gw = (blockIdx.x * blockDim.x + threadIdx.x) >> 5;
    int lane = threadIdx.x & 31;
    if (gw >= n) return;
    int i0 = g_off[gw], i1 = g_off[gw + 1];
    const uint2* pb = (const uint2*)g_pb;
    float4 qa = make_float4(0.f, 0.f, 0.f, 0.f);
    int i = i0;
    for (; i + 7 < i1; i += 8) {
        uint2 b[8];
        #pragma unroll
        for (int k = 0; k < 8; k++) b[k] = pb[g_perm[i + k] * 32 + lane];
        #pragma unroll
        for (int k = 0; k < 8; k++) {
            float2 f = __bfloat1622float2(*(__nv_bfloat162*)&b[k].x);
            float2 g = __bfloat1622float2(*(__nv_bfloat162*)&b[k].y);
            qa.x += f.x; qa.y += f.y; qa.z += g.x; qa.w += g.y;
        }
    }
    for (; i + 3 < i1; i += 4) {
        uint2 b[4];
        #pragma unroll
        for (int k = 0; k < 4; k++) b[k] = pb[g_perm[i + k] * 32 + lane];
        #pragma unroll
        for (int k = 0; k < 4; k++) {
            float2 f = __bfloat1622float2(*(__nv_bfloat162*)&b[k].x);
            float2 g = __bfloat1622float2(*(__nv_bfloat162*)&b[k].y);
            qa.x += f.x; qa.y += f.y; qa.z += g.x; qa.w += g.y;
        }
    }
    for (; i < i1; i++) {
        uint2 b0 = pb[g_perm[i] * 32 + lane];
        float2 f = __bfloat1622float2(*(__nv_bfloat162*)&b0.x);
        float2 g = __bfloat1622float2(*(__nv_bfloat162*)&b0.y);
        qa.x += f.x; qa.y += f.y; qa.z += g.x; qa.w += g.y;
    }
    ((float4*)g_q)[gw * 32 + lane] = qa;
}

// ---------------- bf16 weight fragment image prep ----------------
__global__ void k_prep(const float* w0, const float* w1, const float* w2,
                       const float* w3, const float* w4, const float* w5) {
    int mat = blockIdx.y;
    int t = blockIdx.x * 256 + threadIdx.x;    // 0..2047 per matrix
    if (t >= 2048) return;
    const float* srcs[6] = {w0, w1, w2, w3, w4, w5};
    const float* W = srcs[mat];
    int nt = t >> 7, kp = (t >> 5) & 3, lane = t & 31;
    int n = nt * 8 + (lane >> 2);
    int kb = kp * 32 + (lane & 3) * 2;
    uint4 v;
    v.x = pk(W[(kb + 0)  * 128 + n], W[(kb + 1)  * 128 + n]);
    v.y = pk(W[(kb + 8)  * 128 + n], W[(kb + 9)  * 128 + n]);
    v.z = pk(W[(kb + 16) * 128 + n], W[(kb + 17) * 128 + n]);
    v.w = pk(W[(kb + 24) * 128 + n], W[(kb + 25) * 128 + n]);
    g_wimg[mat * 2048 + t] = v;
}

// ---------------- GEMM layouts ----------------
#define XP    132                    // fp32 tile pitch (floats)
#define BP    68                     // bf16 tile pitch (uint32) — 4r+kl covers 32 banks
#define SM_B  (128 * XP * 4)         // 67584 (gemmB, 256 thr, 2 blocks/SM)
#define SM_AC (64 * XP * 4 + 64 * BP * 4)   // 33792 + 17408 = 51200 (gemmAC, 2 blocks/SM)

// fp32 x tile, NT threads, ROWS rows
template<int NT, int ROWS>
__device__ __forceinline__ void load_xT(float* sX, const float* __restrict__ x,
                                        int rowBase, int n, int tid) {
    const float4* s4 = (const float4*)x;
    #pragma unroll 4
    for (int i = tid; i < ROWS * 32; i += NT) {
        int m = i >> 5, c4 = i & 31;
        float4 v = (rowBase + m < n) ? s4[(size_t)(rowBase + m) * 32 + c4]
                                     : make_float4(0.f, 0.f, 0.f, 0.f);
        *(float4*)(&sX[m * XP + c4 * 4]) = v;
    }
}

// bf16-packed x tile, NT threads, ROWS rows (pitch BP uint32)
template<int NT, int ROWS>
__device__ __forceinline__ void load_xB(uint32_t* sXb, const float* __restrict__ x,
                                        int rowBase, int n, int tid) {
    const float4* s4 = (const float4*)x;
    #pragma unroll 4
    for (int i = tid; i < ROWS * 32; i += NT) {
        int m = i >> 5, c4 = i & 31;
        float4 v = (rowBase + m < n) ? s4[(size_t)(rowBase + m) * 32 + c4]
                                     : make_float4(0.f, 0.f, 0.f, 0.f);
        uint2 o;
        o.x = pk(v.x, v.y);
        o.y = pk(v.z, v.w);
        *(uint2*)(&sXb[m * BP + c4 * 2]) = o;
    }
}

// fragment from fp32 tile (LDS.64 + cvt)
__device__ __forceinline__ void loadA(const float* sX, int row, int kof, uint32_t a[4]) {
    float2 p0 = *(const float2*)&sX[row * XP + kof];
    float2 p1 = *(const float2*)&sX[(row + 8) * XP + kof];
    float2 p2 = *(const float2*)&sX[row * XP + kof + 8];
    float2 p3 = *(const float2*)&sX[(row + 8) * XP + kof + 8];
    a[0] = pk(p0.x, p0.y);
    a[1] = pk(p1.x, p1.y);
    a[2] = pk(p2.x, p2.y);
    a[3] = pk(p3.x, p3.y);
}

// fragment from bf16 tile (4x LDS.32, conflict-free with BP=68)
__device__ __forceinline__ void loadAb(const uint32_t* sXb, int row, int kof, uint32_t a[4]) {
    int base = row * BP + (kof >> 1);
    a[0] = sXb[base];
    a[1] = sXb[base + 8 * BP];
    a[2] = sXb[base + 4];
    a[3] = sXb[base + 8 * BP + 4];
}

// ---- 256-thread (8 warp, 2(wn) x 4(wm)) product: 64-col slab, d[2][8][4] ----
__device__ __forceinline__ void product8(const float* sX, const uint4* __restrict__ gW,
                                         float d[2][8][4], int wm, int wn, int lane) {
    int r0a = (wm * 2 + 0) * 16 + (lane >> 2);
    int r0b = (wm * 2 + 1) * 16 + (lane >> 2);
    int kl = lane & 3;
    for (int kp = 0; kp < 4; kp++) {
        int kof0 = kp * 32 + kl * 2;
        int kof1 = kof0 + 16;
        uint32_t a0[2][4], a1[2][4];
        loadA(sX, r0a, kof0, a0[0]); loadA(sX, r0b, kof0, a0[1]);
        loadA(sX, r0a, kof1, a1[0]); loadA(sX, r0b, kof1, a1[1]);
        #pragma unroll
        for (int j = 0; j < 8; j++) {
            uint4 b = __ldg(&gW[((wn * 8 + j) * 4 + kp) * 32 + lane]);
            mma16(d[0][j], a0[0], b.x, b.y);
            mma16(d[1][j], a0[1], b.x, b.y);
            mma16(d[0][j], a1[0], b.z, b.w);
            mma16(d[1][j], a1[1], b.z, b.w);
        }
    }
}

// ---- gemmAC 64-row block: 8 warps as 2(wm) x 4(wn), 32x32 warp tiles ----
// fp32-source product (for s)
__device__ __forceinline__ void product4f(const float* sX, const uint4* __restrict__ gW,
                                          float d[2][4][4], int wm, int wn, int lane) {
    int r0a = wm * 32 + 0  + (lane >> 2);
    int r0b = wm * 32 + 16 + (lane >> 2);
    int kl = lane & 3;
    for (int kp = 0; kp < 4; kp++) {
        int kof0 = kp * 32 + kl * 2;
        int kof1 = kof0 + 16;
        uint32_t a0[2][4], a1[2][4];
        loadA(sX, r0a, kof0, a0[0]); loadA(sX, r0b, kof0, a0[1]);
        loadA(sX, r0a, kof1, a1[0]); loadA(sX, r0b, kof1, a1[1]);
        #pragma unroll
        for (int j = 0; j < 4; j++) {
            uint4 b = __ldg(&gW[((wn * 4 + j) * 4 + kp) * 32 + lane]);
            mma16(d[0][j], a0[0], b.x, b.y);
            mma16(d[1][j], a0[1], b.x, b.y);
            mma16(d[0][j], a1[0], b.z, b.w);
            mma16(d[1][j], a1[1], b.z, b.w);
        }
    }
}
// bf16-tile product (for q, fsrc)
__device__ __forceinline__ void product4b(const uint32_t* sXb, const uint4* __restrict__ gW,
                                          float d[2][4][4], int wm, int wn, int lane) {
    int r0a = wm * 32 + 0  + (lane >> 2);
    int r0b = wm * 32 + 16 + (lane >> 2);
    int kl = lane & 3;
    for (int kp = 0; kp < 4; kp++) {
        int kof0 = kp * 32 + kl * 2;
        int kof1 = kof0 + 16;
        uint32_t a0[2][4], a1[2][4];
        loadAb(sXb, r0a, kof0, a0[0]); loadAb(sXb, r0b, kof0, a0[1]);
        loadAb(sXb, r0a, kof1, a1[0]); loadAb(sXb, r0b, kof1, a1[1]);
        #pragma unroll
        for (int j = 0; j < 4; j++) {
            uint4 b = __ldg(&gW[((wn * 4 + j) * 4 + kp) * 32 + lane]);
            mma16(d[0][j], a0[0], b.x, b.y);
            mma16(d[1][j], a0[1], b.x, b.y);
            mma16(d[0][j], a1[0], b.z, b.w);
            mma16(d[1][j], a1[1], b.z, b.w);
        }
    }
}

// p = sigmoid(fdst@wr + h@ur + br) * h  -> bf16 g_pb
__global__ void __launch_bounds__(256, 2) k_gemmB(const float* __restrict__ fdst,
                                                  const float* __restrict__ h,
                                                  const float* __restrict__ br, int n) {
    extern __shared__ char sm[];
    float* sX = (float*)sm;
    int tid = threadIdx.x, w = tid >> 5, lane = tid & 31;
    int wm = w >> 1, wn = w & 1;
    int rowBase = blockIdx.x * 128;

    load_xT<256, 128>(sX, fdst, rowBase, n, tid);
    __syncthreads();

    float d[2][8][4];
    #pragma unroll
    for (int i = 0; i < 2; i++)
        #pragma unroll
        for (int j = 0; j < 8; j++)
            #pragma unroll
            for (int q = 0; q < 4; q++) d[i][j][q] = 0.f;

    product8(sX, &g_wimg[2 * 2048], d, wm, wn, lane);
    __syncthreads();
    load_xT<256, 128>(sX, h, rowBase, n, tid);
    __syncthreads();
    product8(sX, &g_wimg[3 * 2048], d, wm, wn, lane);

    #pragma unroll
    for (int i = 0; i < 2; i++) {
        int Rl = (wm * 2 + i) * 16 + (lane >> 2);
        int R = rowBase + Rl;
        #pragma unroll
        for (int j = 0; j < 8; j++) {
            int C = wn * 64 + j * 8 + (lane & 3) * 2;
            float b0 = br[C], b1 = br[C + 1];
            if (R < n) {
                float h0 = sX[Rl * XP + C], h1 = sX[Rl * XP + C + 1];
                g_pb[(size_t)R * 64 + (C >> 1)] =
                    __floats2bfloat162_rn(sigmoidf(d[i][j][0] + b0) * h0,
                                          sigmoidf(d[i][j][1] + b1) * h1);
            }
            if (R + 8 < n) {
                float h0 = sX[(Rl + 8) * XP + C], h1 = sX[(Rl + 8) * XP + C + 1];
                g_pb[(size_t)(R + 8) * 64 + (C >> 1)] =
                    __floats2bfloat162_rn(sigmoidf(d[i][j][2] + b0) * h0,
                                          sigmoidf(d[i][j][3] + b1) * h1);
            }
        }
    }
}

// fused: z = sigmoid(fsrc@wz + s@uz + bz); ht = tanh(fsrc@w + q@u + b);
//        out = (1-z)*s + z*ht   — 64-row blocks, 2 blocks/SM
__global__ void __launch_bounds__(256, 2) k_gemmAC(const float* __restrict__ fsrc,
                                                   const float* __restrict__ bz,
                                                   const float* __restrict__ b,
                                                   float* __restrict__ out, int n) {
    extern __shared__ char sm[];
    float* sS = (float*)sm;                       // s tile fp32 (64 rows), persistent
    uint32_t* sXb = (uint32_t*)(sm + 64 * XP * 4);  // bf16 tile: q, then fsrc
    int tid = threadIdx.x, w = tid >> 5, lane = tid & 31;
    int wm = w >> 2, wn = w & 3;
    int rowBase = blockIdx.x * 64;

    load_xT<256, 64>(sS, g_s, rowBase, n, tid);
    load_xB<256, 64>(sXb, g_q, rowBase, n, tid);
    __syncthreads();

    float d1[2][4][4], d2[2][4][4];
    #pragma unroll
    for (int i = 0; i < 2; i++)
        #pragma unroll
        for (int j = 0; j < 4; j++)
            #pragma unroll
            for (int q = 0; q < 4; q++) { d1[i][j][q] = 0.f; d2[i][j][q] = 0.f; }

    product4f(sS, &g_wimg[4 * 2048], d1, wm, wn, lane);   // s @ uz
    product4b(sXb, &g_wimg[5 * 2048], d2, wm, wn, lane);  // q @ u
    __syncthreads();
    load_xB<256, 64>(sXb, fsrc, rowBase, n, tid);
    __syncthreads();
    product4b(sXb, &g_wimg[0 * 2048], d1, wm, wn, lane);  // + fsrc @ wz
    product4b(sXb, &g_wimg[1 * 2048], d2, wm, wn, lane);  // + fsrc @ w

    #pragma unroll
    for (int i = 0; i < 2; i++) {
        int Rl = wm * 32 + i * 16 + (lane >> 2);
        int R = rowBase + Rl;
        #pragma unroll
        for (int j = 0; j < 4; j++) {
            int C = wn * 32 + j * 8 + (lane & 3) * 2;
            float bz0 = bz[C], bz1 = bz[C + 1];
            float bb0 = b[C],  bb1 = b[C + 1];
            if (R < n) {
                float s0 = sS[Rl * XP + C], s1 = sS[Rl * XP + C + 1];
                float z0 = sigmoidf(d1[i][j][0] + bz0);
                float z1 = sigmoidf(d1[i][j][1] + bz1);
                float t0 = tanh_fast(d2[i][j][0] + bb0);
                float t1 = tanh_fast(d2[i][j][1] + bb1);
                *(float2*)(out + (size_t)R * 128 + C) =
                    make_float2((1.f - z0) * s0 + z0 * t0,
                                (1.f - z1) * s1 + z1 * t1);
            }
            if (R + 8 < n) {
                float s0 = sS[(Rl + 8) * XP + C], s1 = sS[(Rl + 8) * XP + C + 1];
                float z0 = sigmoidf(d1[i][j][2] + bz0);
                float z1 = sigmoidf(d1[i][j][3] + bz1);
                float t0 = tanh_fast(d2[i][j][2] + bb0);
                float t1 = tanh_fast(d2[i][j][3] + bb1);
                *(float2*)(out + (size_t)(R + 8) * 128 + C) =
                    make_float2((1.f - z0) * s0 + z0 * t0,
                                (1.f - z1) * s1 + z1 * t1);
            }
        }
    }
}

// ---------------- launch ----------------
extern "C" void kernel_launch(void* const* d_in, const int* in_sizes, int n_in,
                              void* d_out, int out_size)
{
    const float* h    = (const float*)d_in[0];
    const float* fsrc = (const float*)d_in[1];
    const float* fdst = (const float*)d_in[2];
    const int*   src  = (const int*)d_in[3];
    const int*   dst  = (const int*)d_in[4];
    const float* wz   = (const float*)d_in[5];
    const float* uz   = (const float*)d_in[6];
    const float* bz   = (const float*)d_in[7];
    const float* wr   = (const float*)d_in[8];
    const float* ur   = (const float*)d_in[9];
    const float* br   = (const float*)d_in[10];
    const float* w    = (const float*)d_in[11];
    const float* u    = (const float*)d_in[12];
    const float* b    = (const float*)d_in[13];
    float* out = (float*)d_out;

    int n = in_sizes[0] / 128;
    int e = in_sizes[3];
    if (n > NMAX || e > EMAX) return;

    static cudaStream_t sB = nullptr, sC = nullptr;
    static cudaEvent_t evF = nullptr, evCSR = nullptr, evQ = nullptr, evH = nullptr;
    if (!sB) {
        cudaStreamCreateWithFlags(&sB, cudaStreamNonBlocking);
        cudaStreamCreateWithFlags(&sC, cudaStreamNonBlocking);
        cudaEventCreateWithFlags(&evF, cudaEventDisableTiming);
        cudaEventCreateWithFlags(&evCSR, cudaEventDisableTiming);
        cudaEventCreateWithFlags(&evQ, cudaEventDisableTiming);
        cudaEventCreateWithFlags(&evH, cudaEventDisableTiming);
    }

    cudaFuncSetAttribute(k_gemmB,  cudaFuncAttributeMaxDynamicSharedMemorySize, SM_B);
    cudaFuncSetAttribute(k_gemmAC, cudaFuncAttributeMaxDynamicSharedMemorySize, SM_AC);

    int gemmBlocks = (n + 127) / 128;
    int acBlocks = (n + 63) / 64;
    int nb = (n + 1023) / 1024;

    // fork
    cudaEventRecord(evF, 0);
    cudaStreamWaitEvent(sB, evF, 0);
    cudaStreamWaitEvent(sC, evF, 0);

    // stream C: h -> fp16 (only consumer is reduceS)
    k_hcomp<<<(n * 32 + 255) / 256, 256, 0, sC>>>(h, n);
    cudaEventRecord(evH, sC);

    // stream B: prep + gemmB
    k_prep<<<dim3(8, 6), 256, 0, sB>>>(wz, w, wr, ur, uz, u);
    k_gemmB<<<gemmBlocks, 256, SM_B, sB>>>(fdst, h, br, n);

    // main: CSR chain (g_cnt is zero at entry; k_part re-zeroes it)
    k_hist<<<(e + 255) / 256, 256>>>(dst, e);
    k_part<<<nb, 1024>>>(n);
    k_scanb<<<1, 128>>>(nb);
    k_add<<<(n + 1023) / 1024, 1024>>>(n, e);
    k_scatter<<<(e + 255) / 256, 256>>>(src, dst, e);
    cudaEventRecord(evCSR, 0);

    // s-reduce on main (needs CSR + compressed h)
    cudaStreamWaitEvent(0, evH, 0);
    k_reduceS<<<(n + 7) / 8, 256>>>(n);

    // q-reduce on stream B after CSR + gemmB
    cudaStreamWaitEvent(sB, evCSR, 0);
    k_reduceQ<<<(n + 7) / 8, 256, 0, sB>>>(n);
    cudaEventRecord(evQ, sB);

    // join, then fused gate GEMM
    cudaStreamWaitEvent(0, evQ, 0);
    k_gemmAC<<<acBlocks, 256, SM_AC>>>(fsrc, bz, b, out, n);
}

// round 17
// speedup vs baseline: 1.2813x; 1.0480x over previous
#include <cuda_runtime.h>
#include <cuda_bf16.h>
#include <cuda_fp16.h>
#include <cstdint>

#define NMAX 100000
#define EMAX 1600000

// ---------------- scratch ----------------
__device__ __nv_bfloat162 g_pb[NMAX * 64];   // p compressed to bf16 (gather operand)
__device__ __half2 g_hh[NMAX * 64];          // h compressed to fp16 (gather operand)
__device__ float g_s [NMAX * 128];
__device__ float g_q [NMAX * 128];
__device__ int   g_cnt[NMAX];                // invariant: zero at kernel_launch entry
__device__ int   g_off[NMAX + 1];
__device__ int   g_cur[NMAX];
__device__ int   g_perm[EMAX];
__device__ int   g_bsum[128];
__device__ int   g_bpre[128];
__device__ uint4 g_wimg[6 * 2048];   // 6 bf16 weight images, 32KB each, B-fragment order

__device__ __forceinline__ float sigmoidf(float x) { return 1.0f / (1.0f + __expf(-x)); }
__device__ __forceinline__ float tanh_fast(float x) {
    return __fdividef(2.0f, 1.0f + __expf(-2.0f * x)) - 1.0f;
}
__device__ __forceinline__ uint32_t pk(float lo, float hi) {
    __nv_bfloat162 h = __floats2bfloat162_rn(lo, hi);   // .x = lo (low half)
    return *(uint32_t*)&h;
}

// ---------------- mma.sync m16n8k16 bf16 ----------------
__device__ __forceinline__ void mma16(float* d, const uint32_t* a, uint32_t b0, uint32_t b1) {
    asm("mma.sync.aligned.m16n8k16.row.col.f32.bf16.bf16.f32 "
        "{%0,%1,%2,%3},{%4,%5,%6,%7},{%8,%9},{%0,%1,%2,%3};"
        : "+f"(d[0]), "+f"(d[1]), "+f"(d[2]), "+f"(d[3])
        : "r"(a[0]), "r"(a[1]), "r"(a[2]), "r"(a[3]), "r"(b0), "r"(b1));
}

// ---------------- h -> fp16 compression (off critical path, stream C) ----------------
__global__ void k_hcomp(const float* __restrict__ h, int n) {
    int i = blockIdx.x * blockDim.x + threadIdx.x;
    if (i < n * 32) {
        float4 v = ((const float4*)h)[i];
        g_hh[i * 2 + 0] = __floats2half2_rn(v.x, v.y);
        g_hh[i * 2 + 1] = __floats2half2_rn(v.z, v.w);
    }
}

// ---------------- CSR build ----------------
__global__ void k_hist(const int* __restrict__ dst, int e) {
    int i = blockIdx.x * blockDim.x + threadIdx.x;
    if (i < e) atomicAdd(&g_cnt[dst[i]], 1);
}

// reads counts, zeroes them (restores entry invariant for the next replay)
__global__ void k_part(int n) {
    __shared__ int sm[1024];
    int b = blockIdx.x, t = threadIdx.x;
    int idx = b * 1024 + t;
    int v = 0;
    if (idx < n) { v = g_cnt[idx]; g_cnt[idx] = 0; }
    sm[t] = v;
    __syncthreads();
    #pragma unroll
    for (int off = 1; off < 1024; off <<= 1) {
        int x = (t >= off) ? sm[t - off] : 0;
        __syncthreads();
        sm[t] += x;
        __syncthreads();
    }
    if (idx < n) g_off[idx] = sm[t] - v;
    if (t == 1023) g_bsum[b] = sm[t];
}

__global__ void k_scanb(int nb) {
    __shared__ int sm[128];
    int t = threadIdx.x;
    int v = (t < nb) ? g_bsum[t] : 0;
    sm[t] = v;
    __syncthreads();
    #pragma unroll
    for (int off = 1; off < 128; off <<= 1) {
        int x = (t >= off) ? sm[t - off] : 0;
        __syncthreads();
        sm[t] += x;
        __syncthreads();
    }
    if (t < nb) g_bpre[t] = sm[t] - v;
}

__global__ void k_add(int n, int e) {
    int idx = blockIdx.x * blockDim.x + threadIdx.x;
    if (idx < n) {
        int o = g_off[idx] + g_bpre[idx >> 10];
        g_off[idx] = o;
        g_cur[idx] = o;
    }
    if (idx == 0) g_off[n] = e;
}

__global__ void k_scatter(const int* __restrict__ src, const int* __restrict__ dst, int e) {
    int i = blockIdx.x * blockDim.x + threadIdx.x;
    if (i < e) {
        int d = dst[i];
        int pos = atomicAdd(&g_cur[d], 1);
        g_perm[pos] = src[i];
    }
}

// ---------------- segment reduce, split, 8-deep gather pipeline ----------------
__global__ void k_reduceS(int n) {
    int gw = (blockIdx.x * blockDim.x + threadIdx.x) >> 5;
    int lane = threadIdx.x & 31;
    if (gw >= n) return;
    int i0 = g_off[gw], i1 = g_off[gw + 1];
    const uint2* hh = (const uint2*)g_hh;
    float4 sa = make_float4(0.f, 0.f, 0.f, 0.f);
    int i = i0;
    for (; i + 7 < i1; i += 8) {
        uint2 b[8];
        #pragma unroll
        for (int k = 0; k < 8; k++) b[k] = hh[g_perm[i + k] * 32 + lane];
        #pragma unroll
        for (int k = 0; k < 8; k++) {
            float2 f = __half22float2(*(__half2*)&b[k].x);
            float2 g = __half22float2(*(__half2*)&b[k].y);
            sa.x += f.x; sa.y += f.y; sa.z += g.x; sa.w += g.y;
        }
    }
    for (; i + 3 < i1; i += 4) {
        uint2 b[4];
        #pragma unroll
        for (int k = 0; k < 4; k++) b[k] = hh[g_perm[i + k] * 32 + lane];
        #pragma unroll
        for (int k = 0; k < 4; k++) {
            float2 f = __half22float2(*(__half2*)&b[k].x);
            float2 g = __half22float2(*(__half2*)&b[k].y);
            sa.x += f.x; sa.y += f.y; sa.z += g.x; sa.w += g.y;
        }
    }
    for (; i < i1; i++) {
        uint2 b0 = hh[g_perm[i] * 32 + lane];
        float2 f = __half22float2(*(__half2*)&b0.x);
        float2 g = __half22float2(*(__half2*)&b0.y);
        sa.x += f.x; sa.y += f.y; sa.z += g.x; sa.w += g.y;
    }
    ((float4*)g_s)[gw * 32 + lane] = sa;
}

__global__ void k_reduceQ(int n) {
    int gw = (blockIdx.x * blockDim.x + threadIdx.x) >> 5;
    int lane = threadIdx.x & 31;
    if (gw >= n) return;
    int i0 = g_off[gw], i1 = g_off[gw + 1];
    const uint2* pb = (const uint2*)g_pb;
    float4 qa = make_float4(0.f, 0.f, 0.f, 0.f);
    int i = i0;
    for (; i + 7 < i1; i += 8) {
        uint2 b[8];
        #pragma unroll
        for (int k = 0; k < 8; k++) b[k] = pb[g_perm[i + k] * 32 + lane];
        #pragma unroll
        for (int k = 0; k < 8; k++) {
            float2 f = __bfloat1622float2(*(__nv_bfloat162*)&b[k].x);
            float2 g = __bfloat1622float2(*(__nv_bfloat162*)&b[k].y);
            qa.x += f.x; qa.y += f.y; qa.z += g.x; qa.w += g.y;
        }
    }
    for (; i + 3 < i1; i += 4) {
        uint2 b[4];
        #pragma unroll
        for (int k = 0; k < 4; k++) b[k] = pb[g_perm[i + k] * 32 + lane];
        #pragma unroll
        for (int k = 0; k < 4; k++) {
            float2 f = __bfloat1622float2(*(__nv_bfloat162*)&b[k].x);
            float2 g = __bfloat1622float2(*(__nv_bfloat162*)&b[k].y);
            qa.x += f.x; qa.y += f.y; qa.z += g.x; qa.w += g.y;
        }
    }
    for (; i < i1; i++) {
        uint2 b0 = pb[g_perm[i] * 32 + lane];
        float2 f = __bfloat1622float2(*(__nv_bfloat162*)&b0.x);
        float2 g = __bfloat1622float2(*(__nv_bfloat162*)&b0.y);
        qa.x += f.x; qa.y += f.y; qa.z += g.x; qa.w += g.y;
    }
    ((float4*)g_q)[gw * 32 + lane] = qa;
}

// ---------------- bf16 weight fragment image prep ----------------
__global__ void k_prep(const float* w0, const float* w1, const float* w2,
                       const float* w3, const float* w4, const float* w5) {
    int mat = blockIdx.y;
    int t = blockIdx.x * 256 + threadIdx.x;    // 0..2047 per matrix
    if (t >= 2048) return;
    const float* srcs[6] = {w0, w1, w2, w3, w4, w5};
    const float* W = srcs[mat];
    int nt = t >> 7, kp = (t >> 5) & 3, lane = t & 31;
    int n = nt * 8 + (lane >> 2);
    int kb = kp * 32 + (lane & 3) * 2;
    uint4 v;
    v.x = pk(W[(kb + 0)  * 128 + n], W[(kb + 1)  * 128 + n]);
    v.y = pk(W[(kb + 8)  * 128 + n], W[(kb + 9)  * 128 + n]);
    v.z = pk(W[(kb + 16) * 128 + n], W[(kb + 17) * 128 + n]);
    v.w = pk(W[(kb + 24) * 128 + n], W[(kb + 25) * 128 + n]);
    g_wimg[mat * 2048 + t] = v;
}

// ---------------- GEMM layouts ----------------
#define XP    132                    // fp32 tile pitch (floats)
#define BP    68                     // bf16 tile pitch (uint32)
#define SM_B  (2 * 64 * BP * 4)      // 34816 (gemmB: fdst + h bf16 tiles)
#define SM_AC (64 * XP * 4 + 64 * BP * 4)   // 51200 (gemmAC, 2 blocks/SM)

// fp32 x tile, NT threads, ROWS rows
template<int NT, int ROWS>
__device__ __forceinline__ void load_xT(float* sX, const float* __restrict__ x,
                                        int rowBase, int n, int tid) {
    const float4* s4 = (const float4*)x;
    #pragma unroll 4
    for (int i = tid; i < ROWS * 32; i += NT) {
        int m = i >> 5, c4 = i & 31;
        float4 v = (rowBase + m < n) ? s4[(size_t)(rowBase + m) * 32 + c4]
                                     : make_float4(0.f, 0.f, 0.f, 0.f);
        *(float4*)(&sX[m * XP + c4 * 4]) = v;
    }
}

// bf16-packed x tile, NT threads, ROWS rows (pitch BP uint32)
template<int NT, int ROWS>
__device__ __forceinline__ void load_xB(uint32_t* sXb, const float* __restrict__ x,
                                        int rowBase, int n, int tid) {
    const float4* s4 = (const float4*)x;
    #pragma unroll 4
    for (int i = tid; i < ROWS * 32; i += NT) {
        int m = i >> 5, c4 = i & 31;
        float4 v = (rowBase + m < n) ? s4[(size_t)(rowBase + m) * 32 + c4]
                                     : make_float4(0.f, 0.f, 0.f, 0.f);
        uint2 o;
        o.x = pk(v.x, v.y);
        o.y = pk(v.z, v.w);
        *(uint2*)(&sXb[m * BP + c4 * 2]) = o;
    }
}

// fragment from fp32 tile (LDS.64 + cvt)
__device__ __forceinline__ void loadA(const float* sX, int row, int kof, uint32_t a[4]) {
    float2 p0 = *(const float2*)&sX[row * XP + kof];
    float2 p1 = *(const float2*)&sX[(row + 8) * XP + kof];
    float2 p2 = *(const float2*)&sX[row * XP + kof + 8];
    float2 p3 = *(const float2*)&sX[(row + 8) * XP + kof + 8];
    a[0] = pk(p0.x, p0.y);
    a[1] = pk(p1.x, p1.y);
    a[2] = pk(p2.x, p2.y);
    a[3] = pk(p3.x, p3.y);
}

// fragment from bf16 tile (4x LDS.32, conflict-free with BP=68)
__device__ __forceinline__ void loadAb(const uint32_t* sXb, int row, int kof, uint32_t a[4]) {
    int base = row * BP + (kof >> 1);
    a[0] = sXb[base];
    a[1] = sXb[base + 8 * BP];
    a[2] = sXb[base + 4];
    a[3] = sXb[base + 8 * BP + 4];
}

// ---- 64-row block products: 8 warps as 2(wm) x 4(wn), 32x32 warp tiles ----
// fp32-source product (for s)
__device__ __forceinline__ void product4f(const float* sX, const uint4* __restrict__ gW,
                                          float d[2][4][4], int wm, int wn, int lane) {
    int r0a = wm * 32 + 0  + (lane >> 2);
    int r0b = wm * 32 + 16 + (lane >> 2);
    int kl = lane & 3;
    for (int kp = 0; kp < 4; kp++) {
        int kof0 = kp * 32 + kl * 2;
        int kof1 = kof0 + 16;
        uint32_t a0[2][4], a1[2][4];
        loadA(sX, r0a, kof0, a0[0]); loadA(sX, r0b, kof0, a0[1]);
        loadA(sX, r0a, kof1, a1[0]); loadA(sX, r0b, kof1, a1[1]);
        #pragma unroll
        for (int j = 0; j < 4; j++) {
            uint4 b = __ldg(&gW[((wn * 4 + j) * 4 + kp) * 32 + lane]);
            mma16(d[0][j], a0[0], b.x, b.y);
            mma16(d[1][j], a0[1], b.x, b.y);
            mma16(d[0][j], a1[0], b.z, b.w);
            mma16(d[1][j], a1[1], b.z, b.w);
        }
    }
}
// bf16-tile product (for q, fsrc, fdst, h)
__device__ __forceinline__ void product4b(const uint32_t* sXb, const uint4* __restrict__ gW,
                                          float d[2][4][4], int wm, int wn, int lane) {
    int r0a = wm * 32 + 0  + (lane >> 2);
    int r0b = wm * 32 + 16 + (lane >> 2);
    int kl = lane & 3;
    for (int kp = 0; kp < 4; kp++) {
        int kof0 = kp * 32 + kl * 2;
        int kof1 = kof0 + 16;
        uint32_t a0[2][4], a1[2][4];
        loadAb(sXb, r0a, kof0, a0[0]); loadAb(sXb, r0b, kof0, a0[1]);
        loadAb(sXb, r0a, kof1, a1[0]); loadAb(sXb, r0b, kof1, a1[1]);
        #pragma unroll
        for (int j = 0; j < 4; j++) {
            uint4 b = __ldg(&gW[((wn * 4 + j) * 4 + kp) * 32 + lane]);
            mma16(d[0][j], a0[0], b.x, b.y);
            mma16(d[1][j], a0[1], b.x, b.y);
            mma16(d[0][j], a1[0], b.z, b.w);
            mma16(d[1][j], a1[1], b.z, b.w);
        }
    }
}

// p = sigmoid(fdst@wr + h@ur + br) * h  -> bf16 g_pb
// 64-row blocks, both tiles bf16-resident, 3 blocks/SM target
__global__ void __launch_bounds__(256, 3) k_gemmB(const float* __restrict__ fdst,
                                                  const float* __restrict__ h,
                                                  const float* __restrict__ br, int n) {
    extern __shared__ char sm[];
    uint32_t* sF = (uint32_t*)sm;                    // fdst bf16 tile
    uint32_t* sH = (uint32_t*)(sm + 64 * BP * 4);    // h bf16 tile
    int tid = threadIdx.x, w = tid >> 5, lane = tid & 31;
    int wm = w >> 2, wn = w & 3;
    int rowBase = blockIdx.x * 64;

    load_xB<256, 64>(sF, fdst, rowBase, n, tid);
    load_xB<256, 64>(sH, h, rowBase, n, tid);
    __syncthreads();

    float d[2][4][4];
    #pragma unroll
    for (int i = 0; i < 2; i++)
        #pragma unroll
        for (int j = 0; j < 4; j++)
            #pragma unroll
            for (int q = 0; q < 4; q++) d[i][j][q] = 0.f;

    product4b(sF, &g_wimg[2 * 2048], d, wm, wn, lane);   // fdst @ wr
    product4b(sH, &g_wimg[3 * 2048], d, wm, wn, lane);   // + h @ ur

    #pragma unroll
    for (int i = 0; i < 2; i++) {
        int Rl = wm * 32 + i * 16 + (lane >> 2);
        int R = rowBase + Rl;
        #pragma unroll
        for (int j = 0; j < 4; j++) {
            int C = wn * 32 + j * 8 + (lane & 3) * 2;
            float b0 = br[C], b1 = br[C + 1];
            if (R < n) {
                float2 hv = __bfloat1622float2(*(__nv_bfloat162*)&sH[Rl * BP + (C >> 1)]);
                g_pb[(size_t)R * 64 + (C >> 1)] =
                    __floats2bfloat162_rn(sigmoidf(d[0][j][2*i+0] + b0) * hv.x,
                                          sigmoidf(d[0][j][2*i+1] + b1) * hv.y);
            }
            if (R + 8 < n) {
                float2 hv = __bfloat1622float2(*(__nv_bfloat162*)&sH[(Rl + 8) * BP + (C >> 1)]);
                g_pb[(size_t)(R + 8) * 64 + (C >> 1)] =
                    __floats2bfloat162_rn(sigmoidf(d[1][j][2*i+0] + b0) * hv.x,
                                          sigmoidf(d[1][j][2*i+1] + b1) * hv.y);
            }
        }
    }
}

// fused: z = sigmoid(fsrc@wz + s@uz + bz); ht = tanh(fsrc@w + q@u + b);
//        out = (1-z)*s + z*ht   — 64-row blocks, 2 blocks/SM
__global__ void __launch_bounds__(256, 2) k_gemmAC(const float* __restrict__ fsrc,
                                                   const float* __restrict__ bz,
                                                   const float* __restrict__ b,
                                                   float* __restrict__ out, int n) {
    extern __shared__ char sm[];
    float* sS = (float*)sm;                         // s tile fp32, persistent
    uint32_t* sXb = (uint32_t*)(sm + 64 * XP * 4);  // bf16 tile: q, then fsrc
    int tid = threadIdx.x, w = tid >> 5, lane = tid & 31;
    int wm = w >> 2, wn = w & 3;
    int rowBase = blockIdx.x * 64;

    load_xT<256, 64>(sS, g_s, rowBase, n, tid);
    load_xB<256, 64>(sXb, g_q, rowBase, n, tid);
    __syncthreads();

    float d1[2][4][4], d2[2][4][4];
    #pragma unroll
    for (int i = 0; i < 2; i++)
        #pragma unroll
        for (int j = 0; j < 4; j++)
            #pragma unroll
            for (int q = 0; q < 4; q++) { d1[i][j][q] = 0.f; d2[i][j][q] = 0.f; }

    product4f(sS, &g_wimg[4 * 2048], d1, wm, wn, lane);   // s @ uz
    product4b(sXb, &g_wimg[5 * 2048], d2, wm, wn, lane);  // q @ u
    __syncthreads();
    load_xB<256, 64>(sXb, fsrc, rowBase, n, tid);
    __syncthreads();
    product4b(sXb, &g_wimg[0 * 2048], d1, wm, wn, lane);  // + fsrc @ wz
    product4b(sXb, &g_wimg[1 * 2048], d2, wm, wn, lane);  // + fsrc @ w

    #pragma unroll
    for (int i = 0; i < 2; i++) {
        int Rl = wm * 32 + i * 16 + (lane >> 2);
        int R = rowBase + Rl;
        #pragma unroll
        for (int j = 0; j < 4; j++) {
            int C = wn * 32 + j * 8 + (lane & 3) * 2;
            float bz0 = bz[C], bz1 = bz[C + 1];
            float bb0 = b[C],  bb1 = b[C + 1];
            if (R < n) {
                float s0 = sS[Rl * XP + C], s1 = sS[Rl * XP + C + 1];
                float z0 = sigmoidf(d1[i][j][0] + bz0);
                float z1 = sigmoidf(d1[i][j][1] + bz1);
                float t0 = tanh_fast(d2[i][j][0] + bb0);
                float t1 = tanh_fast(d2[i][j][1] + bb1);
                *(float2*)(out + (size_t)R * 128 + C) =
                    make_float2((1.f - z0) * s0 + z0 * t0,
                                (1.f - z1) * s1 + z1 * t1);
            }
            if (R + 8 < n) {
                float s0 = sS[(Rl + 8) * XP + C], s1 = sS[(Rl + 8) * XP + C + 1];
                float z0 = sigmoidf(d1[i][j][2] + bz0);
                float z1 = sigmoidf(d1[i][j][3] + bz1);
                float t0 = tanh_fast(d2[i][j][2] + bb0);
                float t1 = tanh_fast(d2[i][j][3] + bb1);
                *(float2*)(out + (size_t)(R + 8) * 128 + C) =
                    make_float2((1.f - z0) * s0 + z0 * t0,
                                (1.f - z1) * s1 + z1 * t1);
            }
        }
    }
}

// ---------------- launch ----------------
extern "C" void kernel_launch(void* const* d_in, const int* in_sizes, int n_in,
                              void* d_out, int out_size)
{
    const float* h    = (const float*)d_in[0];
    const float* fsrc = (const float*)d_in[1];
    const float* fdst = (const float*)d_in[2];
    const int*   src  = (const int*)d_in[3];
    const int*   dst  = (const int*)d_in[4];
    const float* wz   = (const float*)d_in[5];
    const float* uz   = (const float*)d_in[6];
    const float* bz   = (const float*)d_in[7];
    const float* wr   = (const float*)d_in[8];
    const float* ur   = (const float*)d_in[9];
    const float* br   = (const float*)d_in[10];
    const float* w    = (const float*)d_in[11];
    const float* u    = (const float*)d_in[12];
    const float* b    = (const float*)d_in[13];
    float* out = (float*)d_out;

    int n = in_sizes[0] / 128;
    int e = in_sizes[3];
    if (n > NMAX || e > EMAX) return;

    static cudaStream_t sB = nullptr, sC = nullptr;
    static cudaEvent_t evF = nullptr, evCSR = nullptr, evQ = nullptr, evH = nullptr;
    if (!sB) {
        cudaStreamCreateWithFlags(&sB, cudaStreamNonBlocking);
        cudaStreamCreateWithFlags(&sC, cudaStreamNonBlocking);
        cudaEventCreateWithFlags(&evF, cudaEventDisableTiming);
        cudaEventCreateWithFlags(&evCSR, cudaEventDisableTiming);
        cudaEventCreateWithFlags(&evQ, cudaEventDisableTiming);
        cudaEventCreateWithFlags(&evH, cudaEventDisableTiming);
    }

    cudaFuncSetAttribute(k_gemmB,  cudaFuncAttributeMaxDynamicSharedMemorySize, SM_B);
    cudaFuncSetAttribute(k_gemmAC, cudaFuncAttributeMaxDynamicSharedMemorySize, SM_AC);

    int acBlocks = (n + 63) / 64;
    int nb = (n + 1023) / 1024;

    // fork
    cudaEventRecord(evF, 0);
    cudaStreamWaitEvent(sB, evF, 0);
    cudaStreamWaitEvent(sC, evF, 0);

    // stream C: h -> fp16 (only consumer is reduceS)
    k_hcomp<<<(n * 32 + 255) / 256, 256, 0, sC>>>(h, n);
    cudaEventRecord(evH, sC);

    // stream B: prep + gemmB
    k_prep<<<dim3(8, 6), 256, 0, sB>>>(wz, w, wr, ur, uz, u);
    k_gemmB<<<acBlocks, 256, SM_B, sB>>>(fdst, h, br, n);

    // main: CSR chain (g_cnt is zero at entry; k_part re-zeroes it)
    k_hist<<<(e + 255) / 256, 256>>>(dst, e);
    k_part<<<nb, 1024>>>(n);
    k_scanb<<<1, 128>>>(nb);
    k_add<<<(n + 1023) / 1024, 1024>>>(n, e);
    k_scatter<<<(e + 255) / 256, 256>>>(src, dst, e);
    cudaEventRecord(evCSR, 0);

    // s-reduce on main (needs CSR + compressed h)
    cudaStreamWaitEvent(0, evH, 0);
    k_reduceS<<<(n + 7) / 8, 256>>>(n);

    // q-reduce on stream B after CSR + gemmB
    cudaStreamWaitEvent(sB, evCSR, 0);
    k_reduceQ<<<(n + 7) / 8, 256, 0, sB>>>(n);
    cudaEventRecord(evQ, sB);

    // join, then fused gate GEMM
    cudaStreamWaitEvent(0, evQ, 0);
    k_gemmAC<<<acBlocks, 256, SM_AC>>>(fsrc, bz, b, out, n);
}